// round 1
// baseline (speedup 1.0000x reference)
#include <cuda_runtime.h>
#include <math.h>

// Problem shape (fixed per reference)
#define BB 4
#define MM 128
#define LL 512
#define DD 768

// Tiling
#define MT 32     // mentions per block (8 warps x 4 m each)
#define DT 128    // feature columns per block (32 lanes x float4)
#define LT 256    // token tile staged in SMEM

#define NEGV (-1e30f)

#define SMEM_BYTES ((LT*DT + MT*LT) * (int)sizeof(float))   // 128KB + 32KB = 160KB

__global__ __launch_bounds__(256, 1)
void mention_repr_kernel(const float* __restrict__ h,
                         const int*   __restrict__ mask,
                         float*       __restrict__ out)
{
    extern __shared__ float smem[];
    float* sh_h = smem;                 // [LT][DT]
    float* sh_a = smem + LT * DT;       // [MT][LT]  additive mask term (0 or -1e30)

    const int b  = blockIdx.z;
    const int m0 = blockIdx.y * MT;
    const int d0 = blockIdx.x * DT;
    const int tid  = threadIdx.x;
    const int lane = tid & 31;
    const int w    = tid >> 5;          // warp id 0..7 -> handles m rows [w*4, w*4+4)

    float acc[4][4];
#pragma unroll
    for (int mi = 0; mi < 4; ++mi)
#pragma unroll
        for (int j = 0; j < 4; ++j)
            acc[mi][j] = -INFINITY;

    for (int lt = 0; lt < LL; lt += LT) {
        // ---- stage h tile [LT][DT] (float4 coalesced) ----
        // LT*DT/4 = 8192 float4 loads, 256 threads -> 32 each
#pragma unroll
        for (int it = 0; it < (LT * DT / 4) / 256; ++it) {
            int idx = it * 256 + tid;
            int l   = idx >> 5;          // DT/4 = 32 float4 per row
            int dq  = idx & 31;
            const float4 v = *(const float4*)(h + ((size_t)b * LL + lt + l) * DD + d0 + dq * 4);
            *(float4*)&sh_h[l * DT + dq * 4] = v;
        }
        // ---- stage additive mask term [MT][LT] ----
#pragma unroll
        for (int it = 0; it < (MT * LT) / 256; ++it) {
            int idx = it * 256 + tid;
            int m   = idx >> 8;          // LT = 256 per row
            int l   = idx & (LT - 1);
            int mk  = mask[((size_t)b * MM + m0 + m) * LL + lt + l];
            sh_a[m * LT + l] = mk ? 0.0f : NEGV;
        }
        __syncthreads();

        const int mm = w * 4;
#pragma unroll 4
        for (int l = 0; l < LT; ++l) {
            const float4 v = *(const float4*)&sh_h[l * DT + lane * 4];
#pragma unroll
            for (int mi = 0; mi < 4; ++mi) {
                const float a = sh_a[(mm + mi) * LT + l];   // warp broadcast
                acc[mi][0] = fmaxf(acc[mi][0], v.x + a);
                acc[mi][1] = fmaxf(acc[mi][1], v.y + a);
                acc[mi][2] = fmaxf(acc[mi][2], v.z + a);
                acc[mi][3] = fmaxf(acc[mi][3], v.w + a);
            }
        }
        __syncthreads();
    }

    // ---- write out [B][M][D], coalesced float4 ----
#pragma unroll
    for (int mi = 0; mi < 4; ++mi) {
        float4 o;
        o.x = acc[mi][0]; o.y = acc[mi][1]; o.z = acc[mi][2]; o.w = acc[mi][3];
        *(float4*)(out + ((size_t)b * MM + m0 + w * 4 + mi) * DD + d0 + lane * 4) = o;
    }
}

extern "C" void kernel_launch(void* const* d_in, const int* in_sizes, int n_in,
                              void* d_out, int out_size)
{
    const float* h    = (const float*)d_in[0];
    const int*   mask = (const int*)  d_in[1];
    float*       out  = (float*)d_out;

    cudaFuncSetAttribute(mention_repr_kernel,
                         cudaFuncAttributeMaxDynamicSharedMemorySize, SMEM_BYTES);

    dim3 grid(DD / DT, MM / MT, BB);   // 6 x 4 x 4 = 96 blocks
    mention_repr_kernel<<<grid, 256, SMEM_BYTES>>>(h, mask, out);
}